// round 3
// baseline (speedup 1.0000x reference)
#include <cuda_runtime.h>
#include <cstdint>

#define BB 8
#define SS 2048
#define DM 1024
#define DH 64
#define M_TOT (BB*SS)   // 16384

// Scratch (device globals — no allocations allowed)
__device__ float g_q [M_TOT*DH];
__device__ float g_k [M_TOT*DH];
__device__ float g_v [M_TOT*DH];
__device__ float g_oh[M_TOT*DH];

typedef unsigned long long u64;

__device__ __forceinline__ u64 dup2(float x){
    u64 r; asm("mov.b64 %0, {%1, %1};" : "=l"(r) : "f"(x)); return r;
}
__device__ __forceinline__ u64 pack2(float a, float b){
    u64 r; asm("mov.b64 %0, {%1, %2};" : "=l"(r) : "f"(a), "f"(b)); return r;
}
__device__ __forceinline__ float2 unpack2(u64 v){
    float2 f; asm("mov.b64 {%0, %1}, %2;" : "=f"(f.x), "=f"(f.y) : "l"(v)); return f;
}
__device__ __forceinline__ void fma2(u64 &d, u64 a, u64 b){
    asm("fma.rn.f32x2 %0, %1, %2, %0;" : "+l"(d) : "l"(a), "l"(b));
}
__device__ __forceinline__ void mul2(u64 &d, u64 a){
    asm("mul.rn.f32x2 %0, %0, %1;" : "+l"(d) : "l"(a));
}

// ---------------------------------------------------------------------------
// Kernel 1: fused QKV projection.  Y[m,n] = sum_d X[m,d] * W[n,d]
// grid = (128, 3), block = 256.  BM=128, BN=64, BK=32. Thread tile 8(m)x4(n),
// f32x2-packed along m.
// ---------------------------------------------------------------------------
__global__ __launch_bounds__(256) void qkv_kernel(
    const float* __restrict__ X,
    const float* __restrict__ Wq,
    const float* __restrict__ Wk,
    const float* __restrict__ Wv)
{
    __shared__ float Xs[32*132];   // [k][m], stride 132 (pad, 16B aligned)
    __shared__ float Wsh[32*68];   // [k][n], stride 68

    const float* W = (blockIdx.y == 0) ? Wq : ((blockIdx.y == 1) ? Wk : Wv);
    float* Y = (blockIdx.y == 0) ? g_q : ((blockIdx.y == 1) ? g_k : g_v);

    const int tid = threadIdx.x;
    const int m0  = blockIdx.x * 128;
    const int tx  = tid & 15;   // n group: n = tx*4 + j
    const int ty  = tid >> 4;   // m group: m = ty*8 + i

    u64 acc[4][4];
    #pragma unroll
    for (int i = 0; i < 4; i++)
        #pragma unroll
        for (int j = 0; j < 4; j++) acc[i][j] = 0ULL;

    for (int kk = 0; kk < DM; kk += 32) {
        // X tile: 128m x 32k, vectorized global read + scattered smem store
        #pragma unroll
        for (int i = 0; i < 4; i++) {
            int lin = tid + i * 256;
            int k4 = lin & 7, m = lin >> 3;
            float4 v = *(const float4*)&X[(size_t)(m0 + m) * DM + kk + k4 * 4];
            Xs[(k4*4+0)*132 + m] = v.x;
            Xs[(k4*4+1)*132 + m] = v.y;
            Xs[(k4*4+2)*132 + m] = v.z;
            Xs[(k4*4+3)*132 + m] = v.w;
        }
        // W tile: 64n x 32k
        #pragma unroll
        for (int i = 0; i < 2; i++) {
            int lin = tid + i * 256;
            int k4 = lin & 7, n = lin >> 3;
            float4 v = *(const float4*)&W[(size_t)n * DM + kk + k4 * 4];
            Wsh[(k4*4+0)*68 + n] = v.x;
            Wsh[(k4*4+1)*68 + n] = v.y;
            Wsh[(k4*4+2)*68 + n] = v.z;
            Wsh[(k4*4+3)*68 + n] = v.w;
        }
        __syncthreads();
        #pragma unroll 8
        for (int k = 0; k < 32; k++) {
            const u64* xp = (const u64*)&Xs[k*132 + ty*8];
            u64 a0 = xp[0], a1 = xp[1], a2 = xp[2], a3 = xp[3];
            float4 wn = *(const float4*)&Wsh[k*68 + tx*4];
            u64 b0 = dup2(wn.x), b1 = dup2(wn.y), b2 = dup2(wn.z), b3 = dup2(wn.w);
            fma2(acc[0][0], a0, b0); fma2(acc[0][1], a0, b1); fma2(acc[0][2], a0, b2); fma2(acc[0][3], a0, b3);
            fma2(acc[1][0], a1, b0); fma2(acc[1][1], a1, b1); fma2(acc[1][2], a1, b2); fma2(acc[1][3], a1, b3);
            fma2(acc[2][0], a2, b0); fma2(acc[2][1], a2, b1); fma2(acc[2][2], a2, b2); fma2(acc[2][3], a2, b3);
            fma2(acc[3][0], a3, b0); fma2(acc[3][1], a3, b1); fma2(acc[3][2], a3, b2); fma2(acc[3][3], a3, b3);
        }
        __syncthreads();
    }
    #pragma unroll
    for (int i = 0; i < 4; i++) {
        float2 a0 = unpack2(acc[i][0]), a1 = unpack2(acc[i][1]);
        float2 a2 = unpack2(acc[i][2]), a3 = unpack2(acc[i][3]);
        size_t m = (size_t)m0 + ty*8 + 2*i;
        *(float4*)&Y[m*DH + tx*4]       = make_float4(a0.x, a1.x, a2.x, a3.x);
        *(float4*)&Y[(m+1)*DH + tx*4]   = make_float4(a0.y, a1.y, a2.y, a3.y);
    }
}

// ---------------------------------------------------------------------------
// Kernel 2: causal flash attention (d=64), fp32, online softmax.
// grid = (16, 8), block = 256.  BQ=64, key tiles of 64.
// Causal balance: block x handles q-tiles {x, 31-x} -> exactly 33 key-tile
// iterations per block (perfectly balanced single wave).
// S-tile thread map: 4(m rows, f32x2 pairs) x 4(contiguous keys 4*tx..4*tx+3).
// PV thread map:     4(m) x 4(h).
// ---------------------------------------------------------------------------
__global__ __launch_bounds__(256) void attn_kernel()
{
    extern __shared__ float sm[];
    float* Qs = sm;                 // [64 h][68 m]
    float* Ks = Qs + 64*68;         // [64 h][68 key]
    float* Vs = Ks + 64*68;         // [64 key][68 h]
    float* Ps = Vs + 64*68;         // [64 key][68 m]

    const int b   = blockIdx.y;
    const int tid = threadIdx.x;
    const int tx  = tid & 15, ty = tid >> 4;

    const float* Qg = g_q  + (size_t)b * SS * DH;
    const float* Kg = g_k  + (size_t)b * SS * DH;
    const float* Vg = g_v  + (size_t)b * SS * DH;
    float*       Og = g_oh + (size_t)b * SS * DH;

    #pragma unroll
    for (int pass = 0; pass < 2; pass++) {
        const int qt = (pass == 0) ? (int)blockIdx.x : (31 - (int)blockIdx.x);
        const int q0 = qt * 64;

        __syncthreads();   // protect smem reuse across passes
        // Load Q tile transposed: Qs[h][m]  (64 rows x 64 h)
        #pragma unroll
        for (int i = 0; i < 4; i++) {
            int lin = tid + i * 256;
            int h4 = lin & 15, m = lin >> 4;
            float4 v = *(const float4*)&Qg[(size_t)(q0 + m) * DH + h4 * 4];
            Qs[(h4*4+0)*68 + m] = v.x;
            Qs[(h4*4+1)*68 + m] = v.y;
            Qs[(h4*4+2)*68 + m] = v.z;
            Qs[(h4*4+3)*68 + m] = v.w;
        }

        float mrow[4], lrow[4], corrv[4];
        u64 o2[2][4];
        #pragma unroll
        for (int i = 0; i < 4; i++) { mrow[i] = -1e30f; lrow[i] = 0.f; }
        #pragma unroll
        for (int i = 0; i < 2; i++)
            #pragma unroll
            for (int j = 0; j < 4; j++) o2[i][j] = 0ULL;

        const int n_kt = qt + 1;   // causal: keys up to q0+63
        for (int kt = 0; kt < n_kt; kt++) {
            const int k0 = kt * 64;
            __syncthreads();
            // K transposed (Ks[h][key]) + V direct (Vs[key][h])
            #pragma unroll
            for (int i = 0; i < 4; i++) {
                int lin = tid + i * 256;
                int h4 = lin & 15, kk = lin >> 4;
                float4 v = *(const float4*)&Kg[(size_t)(k0 + kk) * DH + h4 * 4];
                Ks[(h4*4+0)*68 + kk] = v.x;
                Ks[(h4*4+1)*68 + kk] = v.y;
                Ks[(h4*4+2)*68 + kk] = v.z;
                Ks[(h4*4+3)*68 + kk] = v.w;
                float4 w = *(const float4*)&Vg[(size_t)(k0 + kk) * DH + h4 * 4];
                *(float4*)&Vs[kk*68 + h4*4] = w;
            }
            __syncthreads();

            // ---- S = Q K^T (reduce over h). keys: 4*tx..4*tx+3, rows: ty*4..ty*4+3
            u64 s2[2][4];
            #pragma unroll
            for (int i = 0; i < 2; i++)
                #pragma unroll
                for (int j = 0; j < 4; j++) s2[i][j] = 0ULL;
            #pragma unroll 8
            for (int h = 0; h < 64; h++) {
                const u64* qp = (const u64*)&Qs[h*68 + ty*4];
                u64 a0 = qp[0], a1 = qp[1];
                float4 kv = *(const float4*)&Ks[h*68 + tx*4];
                u64 b0 = dup2(kv.x), b1 = dup2(kv.y), b2 = dup2(kv.z), b3 = dup2(kv.w);
                fma2(s2[0][0], a0, b0); fma2(s2[0][1], a0, b1); fma2(s2[0][2], a0, b2); fma2(s2[0][3], a0, b3);
                fma2(s2[1][0], a1, b0); fma2(s2[1][1], a1, b1); fma2(s2[1][2], a1, b2); fma2(s2[1][3], a1, b3);
            }

            // unpack, scale 1/sqrt(1024), causal mask
            float p[4][4];
            #pragma unroll
            for (int i2 = 0; i2 < 2; i2++)
                #pragma unroll
                for (int j = 0; j < 4; j++) {
                    float2 v = unpack2(s2[i2][j]);
                    p[2*i2  ][j] = v.x;
                    p[2*i2+1][j] = v.y;
                }
            #pragma unroll
            for (int i = 0; i < 4; i++) {
                int q = q0 + ty*4 + i;
                #pragma unroll
                for (int j = 0; j < 4; j++) {
                    int kidx = k0 + tx*4 + j;
                    p[i][j] = (kidx <= q) ? p[i][j] * 0.03125f : -1e30f;
                }
            }

            // online softmax (row spread across 16 tx-lanes of the warp half)
            #pragma unroll
            for (int i = 0; i < 4; i++) {
                float r = fmaxf(fmaxf(p[i][0], p[i][1]), fmaxf(p[i][2], p[i][3]));
                r = fmaxf(r, __shfl_xor_sync(0xffffffffu, r, 1, 16));
                r = fmaxf(r, __shfl_xor_sync(0xffffffffu, r, 2, 16));
                r = fmaxf(r, __shfl_xor_sync(0xffffffffu, r, 4, 16));
                r = fmaxf(r, __shfl_xor_sync(0xffffffffu, r, 8, 16));
                float mnew = fmaxf(mrow[i], r);
                float corr = __expf(mrow[i] - mnew);
                mrow[i] = mnew;
                float lsum = 0.f;
                #pragma unroll
                for (int j = 0; j < 4; j++) {
                    p[i][j] = __expf(p[i][j] - mnew);
                    lsum += p[i][j];
                }
                lsum += __shfl_xor_sync(0xffffffffu, lsum, 1, 16);
                lsum += __shfl_xor_sync(0xffffffffu, lsum, 2, 16);
                lsum += __shfl_xor_sync(0xffffffffu, lsum, 4, 16);
                lsum += __shfl_xor_sync(0xffffffffu, lsum, 8, 16);
                lrow[i] = lrow[i] * corr + lsum;
                corrv[i] = corr;
            }
            // rescale O accumulators (packed pairs along m)
            #pragma unroll
            for (int i2 = 0; i2 < 2; i2++) {
                u64 c2 = pack2(corrv[2*i2], corrv[2*i2+1]);
                #pragma unroll
                for (int j = 0; j < 4; j++) mul2(o2[i2][j], c2);
            }
            // store P tile: Ps[key][m]
            #pragma unroll
            for (int i = 0; i < 4; i++) {
                int m = ty*4 + i;
                #pragma unroll
                for (int j = 0; j < 4; j++)
                    Ps[(tx*4 + j)*68 + m] = p[i][j];
            }
            __syncthreads();

            // ---- O += P V (reduce over keys) ----
            #pragma unroll 8
            for (int kk = 0; kk < 64; kk++) {
                const u64* pp = (const u64*)&Ps[kk*68 + ty*4];
                u64 a0 = pp[0], a1 = pp[1];
                float4 vv = *(const float4*)&Vs[kk*68 + tx*4];
                u64 b0 = dup2(vv.x), b1 = dup2(vv.y), b2 = dup2(vv.z), b3 = dup2(vv.w);
                fma2(o2[0][0], a0, b0); fma2(o2[0][1], a0, b1); fma2(o2[0][2], a0, b2); fma2(o2[0][3], a0, b3);
                fma2(o2[1][0], a1, b0); fma2(o2[1][1], a1, b1); fma2(o2[1][2], a1, b2); fma2(o2[1][3], a1, b3);
            }
        }

        // epilogue: divide by l, write O_head
        #pragma unroll
        for (int i2 = 0; i2 < 2; i2++) {
            u64 c2 = pack2(1.f / lrow[2*i2], 1.f / lrow[2*i2+1]);
            float2 r0, r1, r2, r3;
            mul2(o2[i2][0], c2); r0 = unpack2(o2[i2][0]);
            mul2(o2[i2][1], c2); r1 = unpack2(o2[i2][1]);
            mul2(o2[i2][2], c2); r2 = unpack2(o2[i2][2]);
            mul2(o2[i2][3], c2); r3 = unpack2(o2[i2][3]);
            size_t m = (size_t)q0 + ty*4 + 2*i2;
            *(float4*)&Og[m*DH + tx*4]     = make_float4(r0.x, r1.x, r2.x, r3.x);
            *(float4*)&Og[(m+1)*DH + tx*4] = make_float4(r0.y, r1.y, r2.y, r3.y);
        }
    }
}

// ---------------------------------------------------------------------------
// Kernel 3: output projection. out[m,d] = sum_h Oh[m,h] * Wo[d,h]
// grid = (256, 16), block = 256. BM=64, BN=64, K=64 full.
// ---------------------------------------------------------------------------
__global__ __launch_bounds__(256) void oproj_kernel(
    const float* __restrict__ Wo, float* __restrict__ out)
{
    __shared__ float Os [64*68];   // [h][m]
    __shared__ float Ws2[64*68];   // [h][d]
    const int m0 = blockIdx.x * 64;
    const int d0 = blockIdx.y * 64;
    const int tid = threadIdx.x;
    const int tx = tid & 15, ty = tid >> 4;

    #pragma unroll
    for (int i = 0; i < 4; i++) {
        int lin = tid + i * 256;
        int h4 = lin & 15, r = lin >> 4;
        float4 v = *(const float4*)&g_oh[(size_t)(m0 + r) * DH + h4 * 4];
        Os[(h4*4+0)*68 + r] = v.x;
        Os[(h4*4+1)*68 + r] = v.y;
        Os[(h4*4+2)*68 + r] = v.z;
        Os[(h4*4+3)*68 + r] = v.w;
        float4 w = *(const float4*)&Wo[(size_t)(d0 + r) * DH + h4 * 4];
        Ws2[(h4*4+0)*68 + r] = w.x;
        Ws2[(h4*4+1)*68 + r] = w.y;
        Ws2[(h4*4+2)*68 + r] = w.z;
        Ws2[(h4*4+3)*68 + r] = w.w;
    }
    __syncthreads();

    u64 acc[2][4];
    #pragma unroll
    for (int i = 0; i < 2; i++)
        #pragma unroll
        for (int j = 0; j < 4; j++) acc[i][j] = 0ULL;

    #pragma unroll 8
    for (int h = 0; h < 64; h++) {
        const u64* op = (const u64*)&Os[h*68 + ty*4];
        u64 a0 = op[0], a1 = op[1];
        float4 wv = *(const float4*)&Ws2[h*68 + tx*4];
        u64 b0 = dup2(wv.x), b1 = dup2(wv.y), b2 = dup2(wv.z), b3 = dup2(wv.w);
        fma2(acc[0][0], a0, b0); fma2(acc[0][1], a0, b1); fma2(acc[0][2], a0, b2); fma2(acc[0][3], a0, b3);
        fma2(acc[1][0], a1, b0); fma2(acc[1][1], a1, b1); fma2(acc[1][2], a1, b2); fma2(acc[1][3], a1, b3);
    }
    #pragma unroll
    for (int i2 = 0; i2 < 2; i2++) {
        float2 r0 = unpack2(acc[i2][0]), r1 = unpack2(acc[i2][1]);
        float2 r2 = unpack2(acc[i2][2]), r3 = unpack2(acc[i2][3]);
        size_t m = (size_t)m0 + ty*4 + 2*i2;
        *(float4*)&out[m*DM + d0 + tx*4]     = make_float4(r0.x, r1.x, r2.x, r3.x);
        *(float4*)&out[(m+1)*DM + d0 + tx*4] = make_float4(r0.y, r1.y, r2.y, r3.y);
    }
}

// ---------------------------------------------------------------------------
extern "C" void kernel_launch(void* const* d_in, const int* in_sizes, int n_in,
                              void* d_out, int out_size)
{
    const float* X  = (const float*)d_in[0];
    const float* Wq = (const float*)d_in[1];
    const float* Wk = (const float*)d_in[2];
    const float* Wv = (const float*)d_in[3];
    const float* Wo = (const float*)d_in[4];
    float* out = (float*)d_out;

    qkv_kernel<<<dim3(128, 3), 256>>>(X, Wq, Wk, Wv);

    const int attn_smem = 4 * 64 * 68 * (int)sizeof(float); // ~68 KB
    cudaFuncSetAttribute(attn_kernel, cudaFuncAttributeMaxDynamicSharedMemorySize, attn_smem);
    attn_kernel<<<dim3(16, 8), 256, attn_smem>>>();

    oproj_kernel<<<dim3(256, 16), 256>>>(Wo, out);
}